// round 1
// baseline (speedup 1.0000x reference)
#include <cuda_runtime.h>
#include <cuda_bf16.h>
#include <math.h>

// Problem constants
#define BS    2
#define SEQ   2048
#define NX    768
#define NHEAD 12
#define HD    64
#define MROWS (BS * SEQ)          // 4096

// Scratch (allocation-free rule: __device__ globals)
__device__ float g_q[BS * NHEAD * SEQ * HD];   // [b, h, s, d] per the faithful reshape
__device__ float g_k[BS * NHEAD * SEQ * HD];
__device__ float g_v[BS * NHEAD * SEQ * HD];
__device__ float g_att[BS * SEQ * NX];         // [b, s, h*64+d] (post-transpose layout)

// ---------------------------------------------------------------------------
// Tiled fp32 GEMM: C[M,N] = A[M,K] @ B[K,N] + bias
// BM=BN=64, BK=16, 256 threads, 4x4 microtile per thread.
// mode 0: plain write to C
// mode 1: QKV split epilogue (N=2304): cols [0,768)->g_q, [768,1536)->g_k, rest->g_v
//         (tiles never straddle a 768 boundary since 768 % 64 == 0)
// If A == nullptr, A := g_att (proj GEMM input).
// ---------------------------------------------------------------------------
__global__ __launch_bounds__(256)
void gemm_kernel(const float* __restrict__ A, const float* __restrict__ B,
                 const float* __restrict__ bias, float* __restrict__ C,
                 int M, int N, int K, int mode)
{
    __shared__ float As[16][68];   // A^T tile: As[k][m]
    __shared__ float Bs[16][68];   // Bs[k][n]

    const float* Ap = A ? A : g_att;

    int tid = threadIdx.x;
    int tx = tid & 15;         // n-group
    int ty = tid >> 4;         // m-group
    int n0 = blockIdx.x * 64;
    int m0 = blockIdx.y * 64;

    float acc[4][4];
#pragma unroll
    for (int i = 0; i < 4; i++)
#pragma unroll
        for (int j = 0; j < 4; j++) acc[i][j] = 0.f;

    for (int k0 = 0; k0 < K; k0 += 16) {
        // load A tile (64 rows x 16 k), store transposed
        {
            int mA = tid >> 2;
            int k4 = (tid & 3) * 4;
            float4 a = *(const float4*)&Ap[(size_t)(m0 + mA) * K + k0 + k4];
            As[k4 + 0][mA] = a.x;
            As[k4 + 1][mA] = a.y;
            As[k4 + 2][mA] = a.z;
            As[k4 + 3][mA] = a.w;
            int kB = tid >> 4;
            int n4 = (tid & 15) * 4;
            *(float4*)&Bs[kB][n4] = *(const float4*)&B[(size_t)(k0 + kB) * N + n0 + n4];
        }
        __syncthreads();
#pragma unroll
        for (int kk = 0; kk < 16; kk++) {
            float4 a = *(const float4*)&As[kk][ty * 4];
            float4 b = *(const float4*)&Bs[kk][tx * 4];
            acc[0][0] += a.x * b.x; acc[0][1] += a.x * b.y; acc[0][2] += a.x * b.z; acc[0][3] += a.x * b.w;
            acc[1][0] += a.y * b.x; acc[1][1] += a.y * b.y; acc[1][2] += a.y * b.z; acc[1][3] += a.y * b.w;
            acc[2][0] += a.z * b.x; acc[2][1] += a.z * b.y; acc[2][2] += a.z * b.z; acc[2][3] += a.z * b.w;
            acc[3][0] += a.w * b.x; acc[3][1] += a.w * b.y; acc[3][2] += a.w * b.z; acc[3][3] += a.w * b.w;
        }
        __syncthreads();
    }

    int colg = n0 + tx * 4;  // global col in [0,N)
    float b0 = bias[colg], b1 = bias[colg + 1], b2 = bias[colg + 2], b3 = bias[colg + 3];

    if (mode == 0) {
#pragma unroll
        for (int i = 0; i < 4; i++) {
            int row = m0 + ty * 4 + i;
            float4 o = make_float4(acc[i][0] + b0, acc[i][1] + b1, acc[i][2] + b2, acc[i][3] + b3);
            *(float4*)&C[(size_t)row * N + colg] = o;
        }
    } else {
        int seg = n0 / NX;
        float* dst = (seg == 0) ? g_q : (seg == 1) ? g_k : g_v;
        int c0 = (n0 % NX) + tx * 4;
#pragma unroll
        for (int i = 0; i < 4; i++) {
            int row = m0 + ty * 4 + i;
            float4 o = make_float4(acc[i][0] + b0, acc[i][1] + b1, acc[i][2] + b2, acc[i][3] + b3);
            *(float4*)&dst[(size_t)row * NX + c0] = o;
        }
    }
}

// ---------------------------------------------------------------------------
// Fused causal attention, flash-style online softmax.
// Grid: (32 q-tiles, 12 heads, 2 batch). Block: 256 threads.
// Each thread: row r = tid/4 (of 64 q rows), group g = tid%4.
//   score phase: cols c = g + 4*j (strided, bank-friendly)
//   acc   phase: dims d = g*16 + jj*4 (blocked, float4)
// Faithful masking: masked score = -10000.0 exactly, then + attention_mask.
// ---------------------------------------------------------------------------
__global__ __launch_bounds__(256)
void attn_kernel(const float* __restrict__ am)
{
    extern __shared__ float sm[];
    float* Qs  = sm;                 // 64*68
    float* Ks  = Qs + 64 * 68;       // 64*68
    float* Vs  = Ks + 64 * 68;       // 64*68
    float* Ss  = Vs + 64 * 68;       // 64*68
    float* amS = Ss + 64 * 68;       // 64

    int b = blockIdx.z;
    int h = blockIdx.y;
    int qt = gridDim.x - 1 - blockIdx.x;   // heavy tiles first
    int q0 = qt * 64;
    int tid = threadIdx.x;
    int r = tid >> 2;
    int g = tid & 3;

    const float* qbase = g_q + ((size_t)(b * NHEAD + h) * SEQ) * HD;
    const float* kbase = g_k + ((size_t)(b * NHEAD + h) * SEQ) * HD;
    const float* vbase = g_v + ((size_t)(b * NHEAD + h) * SEQ) * HD;

    // load Q tile (64 rows x 64 d)
    {
        const float4* qg = (const float4*)(qbase + (size_t)q0 * HD);
#pragma unroll
        for (int i = 0; i < 4; i++) {
            int f = tid + 256 * i;        // 0..1023
            int row = f >> 4, d4 = f & 15;
            *(float4*)&Qs[row * 68 + d4 * 4] = qg[row * 16 + d4];
        }
    }

    float m_old = -INFINITY;
    float lsum = 0.f;
    float4 acc[4];
#pragma unroll
    for (int jj = 0; jj < 4; jj++) acc[jj] = make_float4(0.f, 0.f, 0.f, 0.f);

    for (int kt = 0; kt <= qt; kt++) {
        int k0 = kt * 64;
        __syncthreads();   // prev acc phase done with Ks/Vs/Ss; Qs visible (iter 0)
        {
            const float4* kg = (const float4*)(kbase + (size_t)k0 * HD);
            const float4* vg = (const float4*)(vbase + (size_t)k0 * HD);
#pragma unroll
            for (int i = 0; i < 4; i++) {
                int f = tid + 256 * i;
                int row = f >> 4, d4 = f & 15;
                *(float4*)&Ks[row * 68 + d4 * 4] = kg[row * 16 + d4];
                *(float4*)&Vs[row * 68 + d4 * 4] = vg[row * 16 + d4];
            }
            if (tid < 64) amS[tid] = am[(size_t)b * SEQ + k0 + tid];
        }
        __syncthreads();

        // ---- scores: s[j] = Q[r] . K[g+4j] ----
        float s[16];
#pragma unroll
        for (int j = 0; j < 16; j++) s[j] = 0.f;
        for (int d4 = 0; d4 < 16; d4++) {
            float4 q = *(const float4*)&Qs[r * 68 + d4 * 4];
#pragma unroll
            for (int j = 0; j < 16; j++) {
                int c = g + 4 * j;
                float4 k = *(const float4*)&Ks[c * 68 + d4 * 4];
                s[j] += q.x * k.x + q.y * k.y + q.z * k.z + q.w * k.w;
            }
        }

        int qglob = q0 + r;
        float tmax = -INFINITY;
#pragma unroll
        for (int j = 0; j < 16; j++) {
            int c = g + 4 * j;
            int kglob = k0 + c;
            float val = (kglob <= qglob) ? s[j] * 0.125f : -10000.0f;
            val += amS[c];
            s[j] = val;
            tmax = fmaxf(tmax, val);
        }
        tmax = fmaxf(tmax, __shfl_xor_sync(0xffffffffu, tmax, 1));
        tmax = fmaxf(tmax, __shfl_xor_sync(0xffffffffu, tmax, 2));
        float m_new = fmaxf(m_old, tmax);

        float lpart = 0.f;
#pragma unroll
        for (int j = 0; j < 16; j++) {
            float p = __expf(s[j] - m_new);
            Ss[r * 68 + g + 4 * j] = p;
            lpart += p;
        }
        lpart += __shfl_xor_sync(0xffffffffu, lpart, 1);
        lpart += __shfl_xor_sync(0xffffffffu, lpart, 2);

        float scale = __expf(m_old - m_new);
        lsum = lsum * scale + lpart;
        m_old = m_new;
#pragma unroll
        for (int jj = 0; jj < 4; jj++) {
            acc[jj].x *= scale; acc[jj].y *= scale; acc[jj].z *= scale; acc[jj].w *= scale;
        }
        __syncthreads();   // Ss ready for all threads

        // ---- acc: out[r][d] += sum_c P[r][c] * V[c][d], d = g*16 + jj*4 + {0..3}
        for (int c = 0; c < 64; c++) {
            float pv = Ss[r * 68 + c];
#pragma unroll
            for (int jj = 0; jj < 4; jj++) {
                float4 v = *(const float4*)&Vs[c * 68 + g * 16 + jj * 4];
                acc[jj].x += pv * v.x; acc[jj].y += pv * v.y;
                acc[jj].z += pv * v.z; acc[jj].w += pv * v.w;
            }
        }
    }

    float inv = 1.0f / lsum;
    float* ob = g_att + (size_t)b * SEQ * NX + (size_t)(q0 + r) * NX + h * HD + g * 16;
#pragma unroll
    for (int jj = 0; jj < 4; jj++) {
        float4 o = acc[jj];
        o.x *= inv; o.y *= inv; o.z *= inv; o.w *= inv;
        *(float4*)&ob[jj * 4] = o;
    }
}

// ---------------------------------------------------------------------------
extern "C" void kernel_launch(void* const* d_in, const int* in_sizes, int n_in,
                              void* d_out, int out_size)
{
    const float* hs     = (const float*)d_in[0];  // [2,2048,768]
    const float* am     = (const float*)d_in[1];  // [2,1,1,2048]
    const float* w_attn = (const float*)d_in[2];  // [768,2304]
    const float* b_attn = (const float*)d_in[3];  // [2304]
    const float* w_proj = (const float*)d_in[4];  // [768,768]
    const float* b_proj = (const float*)d_in[5];  // [768]
    float* out = (float*)d_out;                   // [2,2048,768]

    // 1) QKV GEMM with split epilogue -> g_q / g_k / g_v
    {
        dim3 grid(3 * NX / 64, MROWS / 64);   // (36, 64)
        gemm_kernel<<<grid, 256>>>(hs, w_attn, b_attn, nullptr, MROWS, 3 * NX, NX, 1);
    }

    // 2) fused causal attention -> g_att
    {
        size_t smem = (size_t)(4 * 64 * 68 + 64) * sizeof(float);  // ~70 KB
        cudaFuncSetAttribute(attn_kernel, cudaFuncAttributeMaxDynamicSharedMemorySize, (int)smem);
        dim3 grid(SEQ / 64, NHEAD, BS);       // (32, 12, 2)
        attn_kernel<<<grid, 256, smem>>>(am);
    }

    // 3) output projection: g_att @ w_proj + b_proj -> out
    {
        dim3 grid(NX / 64, MROWS / 64);       // (12, 64)
        gemm_kernel<<<grid, 256>>>(nullptr, w_proj, b_proj, out, MROWS, NX, NX, 0);
    }
}

// round 3
// speedup vs baseline: 7.7168x; 7.7168x over previous
#include <cuda_runtime.h>
#include <cuda_bf16.h>
#include <math.h>

#define BS    2
#define SEQ   2048
#define NX    768
#define NHEAD 12
#define HD    64
#define MROWS (BS * SEQ)          // 4096

// Scratch (__device__ globals; no allocation allowed)
__device__ float g_q[BS * NHEAD * SEQ * HD];
__device__ float g_k[BS * NHEAD * SEQ * HD];
__device__ float g_v[BS * NHEAD * SEQ * HD];
__device__ float g_att[BS * SEQ * NX];

__device__ __forceinline__ unsigned tf32_of(float x) {
    unsigned u;
    asm("cvt.rna.tf32.f32 %0, %1;" : "=r"(u) : "f"(x));
    return u;
}

__device__ __forceinline__ void mma_tf32(float* c, const unsigned* a, unsigned b0, unsigned b1) {
    asm volatile(
        "mma.sync.aligned.m16n8k8.row.col.f32.tf32.tf32.f32 "
        "{%0,%1,%2,%3},{%4,%5,%6,%7},{%8,%9},{%0,%1,%2,%3};"
        : "+f"(c[0]), "+f"(c[1]), "+f"(c[2]), "+f"(c[3])
        : "r"(a[0]), "r"(a[1]), "r"(a[2]), "r"(a[3]), "r"(b0), "r"(b1));
}

// ---------------------------------------------------------------------------
// tf32 tensor-core GEMM: C[M,N] = A[M,K] @ B[K,N] + bias
// BM=128, BN=128, BK=16. 256 threads = 8 warps (4m x 2n), warp tile 32x64.
// mode 0: write C.  mode 1: QKV split (cols [0,768)->g_q, [768,1536)->g_k, rest g_v).
// A == nullptr means A := g_att.
// ---------------------------------------------------------------------------
#define AS_STRIDE 20
#define BS_STRIDE 136

__global__ __launch_bounds__(256)
void gemm_kernel(const float* __restrict__ A, const float* __restrict__ B,
                 const float* __restrict__ bias, float* __restrict__ C,
                 int M, int N, int K, int mode)
{
    __shared__ unsigned As[128 * AS_STRIDE];   // [m][k], tf32
    __shared__ unsigned Bsm[16 * BS_STRIDE];   // [k][n], tf32

    const float* Ap = A ? A : g_att;

    int tid  = threadIdx.x;
    int lane = tid & 31;
    int wid  = tid >> 5;
    int warpM = wid >> 1;          // 0..3
    int warpN = wid & 1;           // 0..1
    int rowBase = warpM * 32;
    int colBase = warpN * 64;
    int r0 = lane >> 2;            // 0..7
    int c0 = lane & 3;             // 0..3

    int n0 = blockIdx.x * 128;
    int m0 = blockIdx.y * 128;

    float acc[2][8][4];
#pragma unroll
    for (int i = 0; i < 2; i++)
#pragma unroll
        for (int j = 0; j < 8; j++)
#pragma unroll
            for (int e = 0; e < 4; e++) acc[i][j][e] = 0.f;

    for (int k0 = 0; k0 < K; k0 += 16) {
        // stage A tile: 128x16 -> As[m][k]
#pragma unroll
        for (int i = 0; i < 2; i++) {
            int id = tid * 2 + i;              // 0..511 float4 ids
            int row = id >> 2, k4 = (id & 3) * 4;
            float4 a = *(const float4*)&Ap[(size_t)(m0 + row) * K + k0 + k4];
            uint4 p;
            p.x = tf32_of(a.x); p.y = tf32_of(a.y);
            p.z = tf32_of(a.z); p.w = tf32_of(a.w);
            *(uint4*)&As[row * AS_STRIDE + k4] = p;
        }
        // stage B tile: 16x128 -> Bsm[k][n]
#pragma unroll
        for (int i = 0; i < 2; i++) {
            int id = tid * 2 + i;
            int kr = id >> 5, n4 = (id & 31) * 4;
            float4 b = *(const float4*)&B[(size_t)(k0 + kr) * N + n0 + n4];
            uint4 p;
            p.x = tf32_of(b.x); p.y = tf32_of(b.y);
            p.z = tf32_of(b.z); p.w = tf32_of(b.w);
            *(uint4*)&Bsm[kr * BS_STRIDE + n4] = p;
        }
        __syncthreads();

#pragma unroll
        for (int ks = 0; ks < 2; ks++) {
            unsigned a[2][4];
#pragma unroll
            for (int fm = 0; fm < 2; fm++) {
                int r = rowBase + fm * 16 + r0;
                int kk = ks * 8 + c0;
                a[fm][0] = As[r * AS_STRIDE + kk];
                a[fm][1] = As[(r + 8) * AS_STRIDE + kk];
                a[fm][2] = As[r * AS_STRIDE + kk + 4];
                a[fm][3] = As[(r + 8) * AS_STRIDE + kk + 4];
            }
#pragma unroll
            for (int fn = 0; fn < 8; fn++) {
                int kk = ks * 8 + c0;
                int nn = colBase + fn * 8 + r0;
                unsigned b0 = Bsm[kk * BS_STRIDE + nn];
                unsigned b1 = Bsm[(kk + 4) * BS_STRIDE + nn];
                mma_tf32(acc[0][fn], a[0], b0, b1);
                mma_tf32(acc[1][fn], a[1], b0, b1);
            }
        }
        __syncthreads();
    }

    // epilogue
#pragma unroll
    for (int fm = 0; fm < 2; fm++) {
        int rg = m0 + rowBase + fm * 16 + r0;
#pragma unroll
        for (int fn = 0; fn < 8; fn++) {
            int cg = n0 + colBase + fn * 8 + 2 * c0;
            float bb0 = bias[cg], bb1 = bias[cg + 1];
            float2 v0 = make_float2(acc[fm][fn][0] + bb0, acc[fm][fn][1] + bb1);
            float2 v1 = make_float2(acc[fm][fn][2] + bb0, acc[fm][fn][3] + bb1);
            if (mode == 0) {
                *(float2*)&C[(size_t)rg * N + cg] = v0;
                *(float2*)&C[(size_t)(rg + 8) * N + cg] = v1;
            } else {
                float* dst; int cc;
                if (cg < NX)            { dst = g_q; cc = cg; }
                else if (cg < 2 * NX)   { dst = g_k; cc = cg - NX; }
                else                    { dst = g_v; cc = cg - 2 * NX; }
                *(float2*)&dst[(size_t)rg * NX + cc] = v0;
                *(float2*)&dst[(size_t)(rg + 8) * NX + cc] = v1;
            }
        }
    }
}

// ---------------------------------------------------------------------------
// Fused causal flash attention with tf32 mma.
// Q tile 128 rows, K/V tile 64. Block 256 threads = 8 warps; warp owns 16 q rows.
// Q fragments persist in registers. P goes through per-warp smem (stride 68).
// ---------------------------------------------------------------------------
#define KS_STRIDE 68
#define VS_STRIDE 72
#define PS_STRIDE 68

__global__ __launch_bounds__(256)
void attn_kernel(const float* __restrict__ am)
{
    extern __shared__ unsigned sm[];
    unsigned* Ks = sm;                        // 64*68
    unsigned* Vs = Ks + 64 * KS_STRIDE;       // 64*72
    unsigned* Ps = Vs + 64 * VS_STRIDE;       // 128*68
    float*   amS = (float*)(Ps + 128 * PS_STRIDE); // 64

    int b = blockIdx.z;
    int h = blockIdx.y;
    int qt = gridDim.x - 1 - blockIdx.x;      // heavy tiles first
    int q0 = qt * 128;
    int tid = threadIdx.x;
    int lane = tid & 31;
    int wid = tid >> 5;
    int rw = wid * 16;                        // warp's q-row base within tile
    int r0 = lane >> 2;
    int c0 = lane & 3;

    const float* qbase = g_q + ((size_t)(b * NHEAD + h) * SEQ) * HD;
    const float* kbase = g_k + ((size_t)(b * NHEAD + h) * SEQ) * HD;
    const float* vbase = g_v + ((size_t)(b * NHEAD + h) * SEQ) * HD;

    // Q fragments in registers: 8 k-steps x 4 regs
    unsigned qa[8][4];
    {
        const float* qb = qbase + (size_t)(q0 + rw) * HD;
#pragma unroll
        for (int ksx = 0; ksx < 8; ksx++) {
            qa[ksx][0] = tf32_of(qb[(size_t)r0 * HD + ksx * 8 + c0]);
            qa[ksx][1] = tf32_of(qb[(size_t)(r0 + 8) * HD + ksx * 8 + c0]);
            qa[ksx][2] = tf32_of(qb[(size_t)r0 * HD + ksx * 8 + c0 + 4]);
            qa[ksx][3] = tf32_of(qb[(size_t)(r0 + 8) * HD + ksx * 8 + c0 + 4]);
        }
    }

    float oc[8][4];
#pragma unroll
    for (int i = 0; i < 8; i++)
#pragma unroll
        for (int e = 0; e < 4; e++) oc[i][e] = 0.f;
    float m_old[2] = {-INFINITY, -INFINITY};
    float lsum[2]  = {0.f, 0.f};

    int nkt = qt * 2 + 2;
    for (int kt = 0; kt < nkt; kt++) {
        int k0 = kt * 64;
        __syncthreads();
        {
            const float4* kg = (const float4*)(kbase + (size_t)k0 * HD);
            const float4* vg = (const float4*)(vbase + (size_t)k0 * HD);
#pragma unroll
            for (int i = 0; i < 4; i++) {
                int id = tid + 256 * i;       // 0..1023
                int row = id >> 4, d4 = id & 15;
                float4 kv = kg[row * 16 + d4];
                uint4 pk;
                pk.x = tf32_of(kv.x); pk.y = tf32_of(kv.y);
                pk.z = tf32_of(kv.z); pk.w = tf32_of(kv.w);
                *(uint4*)&Ks[row * KS_STRIDE + d4 * 4] = pk;
                float4 vv = vg[row * 16 + d4];
                uint4 pv;
                pv.x = tf32_of(vv.x); pv.y = tf32_of(vv.y);
                pv.z = tf32_of(vv.z); pv.w = tf32_of(vv.w);
                *(uint4*)&Vs[row * VS_STRIDE + d4 * 4] = pv;
            }
            if (tid < 64) amS[tid] = am[(size_t)b * SEQ + k0 + tid];
        }
        __syncthreads();

        // ---- scores S = Q K^T : per warp 16x64 ----
        float sc[8][4];
#pragma unroll
        for (int i = 0; i < 8; i++)
#pragma unroll
            for (int e = 0; e < 4; e++) sc[i][e] = 0.f;

#pragma unroll
        for (int ksx = 0; ksx < 8; ksx++) {
#pragma unroll
            for (int fn = 0; fn < 8; fn++) {
                unsigned b0 = Ks[(fn * 8 + r0) * KS_STRIDE + ksx * 8 + c0];
                unsigned b1 = Ks[(fn * 8 + r0) * KS_STRIDE + ksx * 8 + c0 + 4];
                mma_tf32(sc[fn], qa[ksx], b0, b1);
            }
        }

        // ---- online softmax (2 rows per thread) ----
#pragma unroll
        for (int ri = 0; ri < 2; ri++) {
            int qrow = q0 + rw + r0 + 8 * ri;
            float tmax = -INFINITY;
#pragma unroll
            for (int fn = 0; fn < 8; fn++) {
#pragma unroll
                for (int e = 0; e < 2; e++) {
                    int cl = fn * 8 + 2 * c0 + e;
                    int col = k0 + cl;
                    float v = sc[fn][ri * 2 + e];
                    v = (col <= qrow) ? v * 0.125f : -10000.0f;
                    v += amS[cl];
                    sc[fn][ri * 2 + e] = v;
                    tmax = fmaxf(tmax, v);
                }
            }
            tmax = fmaxf(tmax, __shfl_xor_sync(0xffffffffu, tmax, 1));
            tmax = fmaxf(tmax, __shfl_xor_sync(0xffffffffu, tmax, 2));
            float m_new = fmaxf(m_old[ri], tmax);
            float scale = __expf(m_old[ri] - m_new);
            float lpart = 0.f;
#pragma unroll
            for (int fn = 0; fn < 8; fn++) {
#pragma unroll
                for (int e = 0; e < 2; e++) {
                    int cl = fn * 8 + 2 * c0 + e;
                    float p = __expf(sc[fn][ri * 2 + e] - m_new);
                    lpart += p;
                    Ps[(rw + r0 + 8 * ri) * PS_STRIDE + cl] = tf32_of(p);
                }
            }
            lpart += __shfl_xor_sync(0xffffffffu, lpart, 1);
            lpart += __shfl_xor_sync(0xffffffffu, lpart, 2);
            lsum[ri] = lsum[ri] * scale + lpart;
            m_old[ri] = m_new;
#pragma unroll
            for (int fd = 0; fd < 8; fd++) {
                oc[fd][ri * 2 + 0] *= scale;
                oc[fd][ri * 2 + 1] *= scale;
            }
        }
        __syncwarp();

        // ---- O += P V : per warp 16x64 ----
#pragma unroll
        for (int ksx = 0; ksx < 8; ksx++) {
            unsigned a[4];
            a[0] = Ps[(rw + r0) * PS_STRIDE + ksx * 8 + c0];
            a[1] = Ps[(rw + r0 + 8) * PS_STRIDE + ksx * 8 + c0];
            a[2] = Ps[(rw + r0) * PS_STRIDE + ksx * 8 + c0 + 4];
            a[3] = Ps[(rw + r0 + 8) * PS_STRIDE + ksx * 8 + c0 + 4];
#pragma unroll
            for (int fd = 0; fd < 8; fd++) {
                unsigned b0 = Vs[(ksx * 8 + c0) * VS_STRIDE + fd * 8 + r0];
                unsigned b1 = Vs[(ksx * 8 + c0 + 4) * VS_STRIDE + fd * 8 + r0];
                mma_tf32(oc[fd], a, b0, b1);
            }
        }
        __syncwarp();   // protect Ps until all lanes done reading before next write
    }

    float inv0 = 1.0f / lsum[0];
    float inv1 = 1.0f / lsum[1];
    float* ob = g_att + (size_t)(b * SEQ + q0 + rw + r0) * NX + h * HD;
#pragma unroll
    for (int fd = 0; fd < 8; fd++) {
        int cc = fd * 8 + 2 * c0;
        *(float2*)&ob[cc] = make_float2(oc[fd][0] * inv0, oc[fd][1] * inv0);
        *(float2*)&ob[(size_t)8 * NX + cc] = make_float2(oc[fd][2] * inv1, oc[fd][3] * inv1);
    }
}

// ---------------------------------------------------------------------------
extern "C" void kernel_launch(void* const* d_in, const int* in_sizes, int n_in,
                              void* d_out, int out_size)
{
    const float* hs     = (const float*)d_in[0];
    const float* am     = (const float*)d_in[1];
    const float* w_attn = (const float*)d_in[2];
    const float* b_attn = (const float*)d_in[3];
    const float* w_proj = (const float*)d_in[4];
    const float* b_proj = (const float*)d_in[5];
    float* out = (float*)d_out;

    // 1) QKV GEMM (split epilogue)
    {
        dim3 grid(3 * NX / 128, MROWS / 128);   // (18, 32)
        gemm_kernel<<<grid, 256>>>(hs, w_attn, b_attn, nullptr, MROWS, 3 * NX, NX, 1);
    }

    // 2) fused attention
    {
        size_t smem = (size_t)(64 * KS_STRIDE + 64 * VS_STRIDE + 128 * PS_STRIDE) * 4 + 64 * 4;
        cudaFuncSetAttribute(attn_kernel, cudaFuncAttributeMaxDynamicSharedMemorySize, (int)smem);
        dim3 grid(SEQ / 128, NHEAD, BS);        // (16, 12, 2)
        attn_kernel<<<grid, 256, smem>>>(am);
    }

    // 3) projection GEMM
    {
        dim3 grid(NX / 128, MROWS / 128);       // (6, 32)
        gemm_kernel<<<grid, 256>>>(nullptr, w_proj, b_proj, out, MROWS, NX, NX, 0);
    }
}